// round 12
// baseline (speedup 1.0000x reference)
#include <cuda_runtime.h>
#include <cuda_fp16.h>
#include <cstdint>

#define HID  256
#define QN   200
#define NPIX (256 * 256)
#define NB   4
#define NROW (NB * QN)    // 800 merged (b,q) rows

#define MROWS   13        // ceil(200/16) query row-tiles of 16
#define KSTEPS  16        // 256 / 16
#define PTILE   64        // pixels per GEMM CTA
#define BSTRIDE 132       // smem row stride in u32 (k-pairs), conflict-free
#define NWARP   13        // one warp per m-row tile (R10 shape)
#define GTHREADS (NWARP * 32)

#define QSTRIDE 260       // fused-MLP smem row stride (f32), conflict-free
#define WSTRIDE 36        // fused-MLP W-tile stride (f32)

// ---------------------------------------------------------------------------
// Device scratch (allocation-free)
// ---------------------------------------------------------------------------
__device__ float g_me[NROW * HID];                          // mask_embed fp32
__device__ uint4 g_AH[NB * MROWS * KSTEPS * 32];            // A fragments (fp16)

// ---------------------------------------------------------------------------
// mma.sync m16n8k16 fp16 in / fp32 accum + ldmatrix (baseline PTX, sm_100 OK)
// ---------------------------------------------------------------------------
__device__ __forceinline__ void mma_f16(float* d, uint4 a, uint32_t b0, uint32_t b1) {
    asm volatile(
        "mma.sync.aligned.m16n8k16.row.col.f32.f16.f16.f32 "
        "{%0,%1,%2,%3}, {%4,%5,%6,%7}, {%8,%9}, {%0,%1,%2,%3};"
        : "+f"(d[0]), "+f"(d[1]), "+f"(d[2]), "+f"(d[3])
        : "r"(a.x), "r"(a.y), "r"(a.z), "r"(a.w), "r"(b0), "r"(b1));
}

__device__ __forceinline__ void ldsm_x4(uint32_t& r0, uint32_t& r1,
                                        uint32_t& r2, uint32_t& r3, uint32_t addr) {
    asm volatile("ldmatrix.sync.aligned.m8n8.x4.shared.b16 {%0,%1,%2,%3}, [%4];"
        : "=r"(r0), "=r"(r1), "=r"(r2), "=r"(r3) : "r"(addr));
}

__device__ __forceinline__ uint32_t pack_f16(float a, float b) {
    __half2 h = __floats2half2_rn(a, b);
    return *reinterpret_cast<uint32_t*>(&h);
}

// ---------------------------------------------------------------------------
// Fused MLP: both layers in one kernel. Block = 32 merged rows, 256 threads.
// h = relu(q@w1^T + b1) kept in smem; me = h@w2^T + b2 -> g_me.
// W streamed in 32x32 transposed tiles (sW[k][n], stride 36).
// Thread (r2 = tid/8, c8 = tid%8) owns row r2, cols c8*4..c8*4+3 per n-tile.
// ---------------------------------------------------------------------------
__global__ __launch_bounds__(256) void fused_mlp_kernel(
    const float* __restrict__ queries,
    const float* __restrict__ w1, const float* __restrict__ b1,
    const float* __restrict__ w2, const float* __restrict__ b2)
{
    extern __shared__ float smem[];
    float* sQ = smem;                       // [32][QSTRIDE]
    float* sH = smem + 32 * QSTRIDE;        // [32][QSTRIDE]
    float* sW = sH + 32 * QSTRIDE;          // [32][WSTRIDE] transposed W tile

    const int tid = threadIdx.x;
    const int r0  = blockIdx.x * 32;        // merged row base (25 blocks x 32 = 800)
    const int r2  = tid >> 3;
    const int c8  = tid & 7;
    const int wn  = tid >> 3;               // W-tile load: n row
    const int wkq = (tid & 7) * 4;          // W-tile load: k quad

    // load queries rows r0..r0+31 (coalesced float4)
    for (int i = tid; i < 32 * 64; i += 256) {
        const int r = i >> 6, c4 = i & 63;
        float4 v = reinterpret_cast<const float4*>(queries + (size_t)(r0 + r) * HID)[c4];
        *reinterpret_cast<float4*>(&sQ[r * QSTRIDE + c4 * 4]) = v;
    }
    __syncthreads();

    // ---- layer 1: sQ -> sH (relu) ----
    for (int n0 = 0; n0 < HID; n0 += 32) {
        float acc[4] = {};
        for (int k0 = 0; k0 < HID; k0 += 32) {
            __syncthreads();
            {
                float4 wv = *reinterpret_cast<const float4*>(
                    w1 + (size_t)(n0 + wn) * HID + k0 + wkq);
                sW[(wkq + 0) * WSTRIDE + wn] = wv.x;
                sW[(wkq + 1) * WSTRIDE + wn] = wv.y;
                sW[(wkq + 2) * WSTRIDE + wn] = wv.z;
                sW[(wkq + 3) * WSTRIDE + wn] = wv.w;
            }
            __syncthreads();
            #pragma unroll
            for (int k = 0; k < 32; k++) {
                const float a = sQ[r2 * QSTRIDE + k0 + k];
                float4 w = *reinterpret_cast<const float4*>(&sW[k * WSTRIDE + c8 * 4]);
                acc[0] = fmaf(a, w.x, acc[0]);
                acc[1] = fmaf(a, w.y, acc[1]);
                acc[2] = fmaf(a, w.z, acc[2]);
                acc[3] = fmaf(a, w.w, acc[3]);
            }
        }
        float4 o;
        o.x = acc[0] + b1[n0 + c8 * 4 + 0];
        o.y = acc[1] + b1[n0 + c8 * 4 + 1];
        o.z = acc[2] + b1[n0 + c8 * 4 + 2];
        o.w = acc[3] + b1[n0 + c8 * 4 + 3];
        o.x = o.x > 0.f ? o.x : 0.f;
        o.y = o.y > 0.f ? o.y : 0.f;
        o.z = o.z > 0.f ? o.z : 0.f;
        o.w = o.w > 0.f ? o.w : 0.f;
        *reinterpret_cast<float4*>(&sH[r2 * QSTRIDE + n0 + c8 * 4]) = o;
    }

    // ---- layer 2: sH -> g_me ----
    for (int n0 = 0; n0 < HID; n0 += 32) {
        float acc[4] = {};
        for (int k0 = 0; k0 < HID; k0 += 32) {
            __syncthreads();   // also orders layer-1 sH writes before reads
            {
                float4 wv = *reinterpret_cast<const float4*>(
                    w2 + (size_t)(n0 + wn) * HID + k0 + wkq);
                sW[(wkq + 0) * WSTRIDE + wn] = wv.x;
                sW[(wkq + 1) * WSTRIDE + wn] = wv.y;
                sW[(wkq + 2) * WSTRIDE + wn] = wv.z;
                sW[(wkq + 3) * WSTRIDE + wn] = wv.w;
            }
            __syncthreads();
            #pragma unroll
            for (int k = 0; k < 32; k++) {
                const float a = sH[r2 * QSTRIDE + k0 + k];
                float4 w = *reinterpret_cast<const float4*>(&sW[k * WSTRIDE + c8 * 4]);
                acc[0] = fmaf(a, w.x, acc[0]);
                acc[1] = fmaf(a, w.y, acc[1]);
                acc[2] = fmaf(a, w.z, acc[2]);
                acc[3] = fmaf(a, w.w, acc[3]);
            }
        }
        float4 o;
        o.x = acc[0] + b2[n0 + c8 * 4 + 0];
        o.y = acc[1] + b2[n0 + c8 * 4 + 1];
        o.z = acc[2] + b2[n0 + c8 * 4 + 2];
        o.w = acc[3] + b2[n0 + c8 * 4 + 3];
        *reinterpret_cast<float4*>(g_me + (size_t)(r0 + r2) * HID + n0 + c8 * 4) = o;
    }
}

// ---------------------------------------------------------------------------
// Pack mask_embed into per-lane A fragments (single fp16 rounding).
// ---------------------------------------------------------------------------
__global__ __launch_bounds__(512) void pack_kernel()
{
    const int blk = blockIdx.x;              // b*MROWS + mr
    const int b   = blk / MROWS;
    const int mr  = blk % MROWS;
    const int ks  = threadIdx.x >> 5;        // 0..15
    const int lane = threadIdx.x & 31;
    const int g = lane >> 2, i4 = lane & 3;

    const int r0 = mr * 16 + g;
    const int r1 = r0 + 8;
    const int c0 = ks * 16 + i4 * 2;

    float v[2][4];
    #pragma unroll
    for (int rr = 0; rr < 2; rr++) {
        const int r = rr ? r1 : r0;
        #pragma unroll
        for (int cc = 0; cc < 4; cc++) {
            const int c = c0 + (cc >> 1) * 8 + (cc & 1);
            v[rr][cc] = (r < QN) ? g_me[(size_t)(b * QN + r) * HID + c] : 0.f;
        }
    }

    uint4 ah;
    ah.x = pack_f16(v[0][0], v[0][1]);
    ah.y = pack_f16(v[1][0], v[1][1]);
    ah.z = pack_f16(v[0][2], v[0][3]);
    ah.w = pack_f16(v[1][2], v[1][3]);

    g_AH[((size_t)(b * MROWS + mr) * KSTEPS + ks) * 32 + lane] = ah;
}

// ---------------------------------------------------------------------------
// GEMM (R10 structure — best known): out[b,q,p] = sum_c me[b,q,c]*mf[b,c,p]
// CTA = 64-pixel stripe; 13 warps, one m-tile each, rotated by blockIdx.x.
// B fragments via ldmatrix.x4 from [pixel][kpair] smem (stride 132).
// Only change vs R10: ks unroll 4 -> 8 (deeper A-LDG batching).
// ---------------------------------------------------------------------------
__global__ __launch_bounds__(GTHREADS) void gemm_kernel(
    const float* __restrict__ mf, float* __restrict__ out)
{
    extern __shared__ uint32_t sB[];               // [64 pixels][BSTRIDE kpairs]

    const int tid  = threadIdx.x;
    const int lane = tid & 31;
    const int w    = tid >> 5;
    const int g    = lane >> 2, i4 = lane & 3;

    const int p0 = blockIdx.x * PTILE;
    const int b  = blockIdx.y;

    const float* mfb  = mf  + (size_t)b * HID * NPIX;
    float*       outb = out + (size_t)b * QN  * NPIX;

    // ---- load + convert B tile: 64 pixels x 256 channels, fp32 -> fp16 ----
    for (int idx = tid; idx < 128 * 16; idx += GTHREADS) {
        const int cp  = idx >> 4;
        const int p4  = idx & 15;
        const float* r0 = mfb + (size_t)(2 * cp)     * NPIX + p0 + p4 * 4;
        const float* r1 = mfb + (size_t)(2 * cp + 1) * NPIX + p0 + p4 * 4;
        float4 v0 = *reinterpret_cast<const float4*>(r0);
        float4 v1 = *reinterpret_cast<const float4*>(r1);
        const float a0[4] = {v0.x, v0.y, v0.z, v0.w};
        const float a1[4] = {v1.x, v1.y, v1.z, v1.w};
        #pragma unroll
        for (int s = 0; s < 4; s++) {
            const int j = (s + p4) & 3;            // stagger -> fewer store conflicts
            sB[(uint32_t)(p4 * 4 + j) * BSTRIDE + cp] = pack_f16(a0[j], a1[j]);
        }
    }
    __syncthreads();

    // ---- compute: warp owns m-tile (w + bx) % 13 ----
    const int mr = (w + (int)blockIdx.x) % NWARP;

    float acc[8][4];
    #pragma unroll
    for (int n = 0; n < 8; n++)
        #pragma unroll
        for (int x = 0; x < 4; x++) acc[n][x] = 0.f;

    const uint4* pAH = g_AH + ((size_t)(b * MROWS + mr) * KSTEPS) * 32 + lane;

    // ldmatrix base: quad q8 selects matrix within x4 (two n-chunks' b0/b1)
    const int q8 = lane >> 3;
    const int r8 = lane & 7;
    const uint32_t sB_addr = (uint32_t)__cvta_generic_to_shared(sB);
    const uint32_t lm_base = sB_addr +
        (uint32_t)((((q8 >> 1) * 8 + r8) * BSTRIDE + (q8 & 1) * 4) * 4);
    const uint32_t J_STRIDE = (uint32_t)(16 * BSTRIDE * 4);   // 2 n-chunks of rows

    #pragma unroll 8
    for (int ks = 0; ks < KSTEPS; ks++) {
        const uint4 ah = pAH[ks * 32];
        const uint32_t ka = lm_base + (uint32_t)(ks * 32);    // ks*8 u32 cols
        #pragma unroll
        for (int j = 0; j < 4; j++) {
            uint32_t b0, b1, b2, b3;
            ldsm_x4(b0, b1, b2, b3, ka + (uint32_t)j * J_STRIDE);
            mma_f16(acc[2 * j],     ah, b0, b1);
            mma_f16(acc[2 * j + 1], ah, b2, b3);
        }
    }

    // ---- epilogue: D frag (16x8) rows = queries, cols = pixel pairs ----
    {
        const int q = mr * 16 + g;
        if (q < QN) {
            float* o = outb + (size_t)q * NPIX + p0 + i4 * 2;
            #pragma unroll
            for (int nc = 0; nc < 8; nc++)
                *reinterpret_cast<float2*>(o + nc * 8) = make_float2(acc[nc][0], acc[nc][1]);
        }
        const int q2 = q + 8;
        if (q2 < QN) {
            float* o2 = outb + (size_t)q2 * NPIX + p0 + i4 * 2;
            #pragma unroll
            for (int nc = 0; nc < 8; nc++)
                *reinterpret_cast<float2*>(o2 + nc * 8) = make_float2(acc[nc][2], acc[nc][3]);
        }
    }
}

// ---------------------------------------------------------------------------
extern "C" void kernel_launch(void* const* d_in, const int* in_sizes, int n_in,
                              void* d_out, int out_size)
{
    const float* queries = (const float*)d_in[0];  // (4, 200, 256)
    const float* mf      = (const float*)d_in[1];  // (4, 256, 256, 256)
    const float* w1      = (const float*)d_in[2];
    const float* b1      = (const float*)d_in[3];
    const float* w2      = (const float*)d_in[4];
    const float* b2      = (const float*)d_in[5];
    float* out = (float*)d_out;                    // (4, 200, 256, 256)

    const int mlp_smem = (2 * 32 * QSTRIDE + 32 * WSTRIDE) * (int)sizeof(float); // 71168 B
    cudaFuncSetAttribute(fused_mlp_kernel, cudaFuncAttributeMaxDynamicSharedMemorySize, mlp_smem);

    const int smem = PTILE * BSTRIDE * (int)sizeof(uint32_t);   // 33792 B
    cudaFuncSetAttribute(gemm_kernel, cudaFuncAttributeMaxDynamicSharedMemorySize, smem);

    fused_mlp_kernel<<<NROW / 32, 256, mlp_smem>>>(queries, w1, b1, w2, b2);
    pack_kernel<<<NB * MROWS, 512>>>();
    gemm_kernel<<<dim3(NPIX / PTILE, NB), GTHREADS, smem>>>(mf, out);
}

// round 14
// speedup vs baseline: 1.8201x; 1.8201x over previous
#include <cuda_runtime.h>
#include <cuda_fp16.h>
#include <cstdint>

#define HID  256
#define QN   200
#define NPIX (256 * 256)
#define NB   4
#define NROW (NB * QN)    // 800 merged (b,q) rows

#define MROWS   13        // ceil(200/16) query row-tiles of 16
#define KSTEPS  16        // 256 / 16
#define PTILE   64        // pixels per GEMM CTA
#define BSTRIDE 132       // smem row stride in u32 (k-pairs), conflict-free
#define NWARP   13        // one warp per m-row tile (R10 shape)
#define GTHREADS (NWARP * 32)

#define LSTRIDE 36        // layer-kernel transposed panel stride (f32)

// ---------------------------------------------------------------------------
// Device scratch (allocation-free)
// ---------------------------------------------------------------------------
__device__ float g_h [NROW * HID];                          // hidden fp32
__device__ float g_me[NROW * HID];                          // mask_embed fp32
__device__ uint4 g_AH[NB * MROWS * KSTEPS * 32];            // A fragments (fp16)

// ---------------------------------------------------------------------------
// mma.sync m16n8k16 fp16 in / fp32 accum + ldmatrix (baseline PTX, sm_100 OK)
// ---------------------------------------------------------------------------
__device__ __forceinline__ void mma_f16(float* d, uint4 a, uint32_t b0, uint32_t b1) {
    asm volatile(
        "mma.sync.aligned.m16n8k16.row.col.f32.f16.f16.f32 "
        "{%0,%1,%2,%3}, {%4,%5,%6,%7}, {%8,%9}, {%0,%1,%2,%3};"
        : "+f"(d[0]), "+f"(d[1]), "+f"(d[2]), "+f"(d[3])
        : "r"(a.x), "r"(a.y), "r"(a.z), "r"(a.w), "r"(b0), "r"(b1));
}

__device__ __forceinline__ void ldsm_x4(uint32_t& r0, uint32_t& r1,
                                        uint32_t& r2, uint32_t& r3, uint32_t addr) {
    asm volatile("ldmatrix.sync.aligned.m8n8.x4.shared.b16 {%0,%1,%2,%3}, [%4];"
        : "=r"(r0), "=r"(r1), "=r"(r2), "=r"(r3) : "r"(addr));
}

__device__ __forceinline__ uint32_t pack_f16(float a, float b) {
    __half2 h = __floats2half2_rn(a, b);
    return *reinterpret_cast<uint32_t*>(&h);
}

// ---------------------------------------------------------------------------
// MLP layer: C[r,n] = act( sum_k A[r,k] * W[n,k] + bias[n] )
// 32 rows x 32 cols per block, grid (25, 8) = 200 blocks.
// FULL K=256 panels of A and W staged transposed in smem (stride 36),
// one sync, then a straight 256-iteration FMA loop.
// FIXED staging map: c4 = (tid&3) + kk*4 covers ALL 64 float4s per row
// (R13 bug: kq = ljb + kk*16 covered only 1/4 of the columns).
// ---------------------------------------------------------------------------
template<bool RELU>
__global__ __launch_bounds__(128) void layer_kernel(
    const float* __restrict__ A, const float* __restrict__ W,
    const float* __restrict__ bias, float* __restrict__ C)
{
    extern __shared__ float lsm[];
    float* sA = lsm;                        // [256 k][LSTRIDE rows]
    float* sW = lsm + HID * LSTRIDE;        // [256 k][LSTRIDE cols]

    const int tid = threadIdx.x;
    const int r0 = blockIdx.x * 32;
    const int n0 = blockIdx.y * 32;
    const int tr = tid & 7;        // row group: 4 rows
    const int tc = tid >> 3;       // col group: 2 cols (0..15)
    const int lrow = tid >> 2;     // 0..31: panel row/col to load
    const int lq   = tid & 3;      // float4 phase within row

    #pragma unroll
    for (int kk = 0; kk < 16; kk++) {
        const int c4 = lq + kk * 4;          // float4 index 0..63 (all covered)
        const int k0 = c4 * 4;               // k base for this float4
        float4 va = *reinterpret_cast<const float4*>(A + (size_t)(r0 + lrow) * HID + k0);
        sA[(k0 + 0) * LSTRIDE + lrow] = va.x;
        sA[(k0 + 1) * LSTRIDE + lrow] = va.y;
        sA[(k0 + 2) * LSTRIDE + lrow] = va.z;
        sA[(k0 + 3) * LSTRIDE + lrow] = va.w;
        float4 vw = *reinterpret_cast<const float4*>(W + (size_t)(n0 + lrow) * HID + k0);
        sW[(k0 + 0) * LSTRIDE + lrow] = vw.x;
        sW[(k0 + 1) * LSTRIDE + lrow] = vw.y;
        sW[(k0 + 2) * LSTRIDE + lrow] = vw.z;
        sW[(k0 + 3) * LSTRIDE + lrow] = vw.w;
    }
    __syncthreads();

    float acc[4][2] = {};
    #pragma unroll 8
    for (int k = 0; k < HID; k++) {
        float4 a = *reinterpret_cast<const float4*>(&sA[k * LSTRIDE + tr * 4]);
        float2 w = *reinterpret_cast<const float2*>(&sW[k * LSTRIDE + tc * 2]);
        acc[0][0] = fmaf(a.x, w.x, acc[0][0]); acc[0][1] = fmaf(a.x, w.y, acc[0][1]);
        acc[1][0] = fmaf(a.y, w.x, acc[1][0]); acc[1][1] = fmaf(a.y, w.y, acc[1][1]);
        acc[2][0] = fmaf(a.z, w.x, acc[2][0]); acc[2][1] = fmaf(a.z, w.y, acc[2][1]);
        acc[3][0] = fmaf(a.w, w.x, acc[3][0]); acc[3][1] = fmaf(a.w, w.y, acc[3][1]);
    }

    const float b0 = bias[n0 + tc * 2];
    const float b1 = bias[n0 + tc * 2 + 1];
    #pragma unroll
    for (int r = 0; r < 4; r++) {
        float v0 = acc[r][0] + b0;
        float v1 = acc[r][1] + b1;
        if (RELU) { v0 = v0 > 0.f ? v0 : 0.f; v1 = v1 > 0.f ? v1 : 0.f; }
        *reinterpret_cast<float2*>(C + (size_t)(r0 + tr * 4 + r) * HID + n0 + tc * 2)
            = make_float2(v0, v1);
    }
}

// ---------------------------------------------------------------------------
// Pack mask_embed into per-lane A fragments (single fp16 rounding).
// ---------------------------------------------------------------------------
__global__ __launch_bounds__(512) void pack_kernel()
{
    const int blk = blockIdx.x;              // b*MROWS + mr
    const int b   = blk / MROWS;
    const int mr  = blk % MROWS;
    const int ks  = threadIdx.x >> 5;        // 0..15
    const int lane = threadIdx.x & 31;
    const int g = lane >> 2, i4 = lane & 3;

    const int r0 = mr * 16 + g;
    const int r1 = r0 + 8;
    const int c0 = ks * 16 + i4 * 2;

    float v[2][4];
    #pragma unroll
    for (int rr = 0; rr < 2; rr++) {
        const int r = rr ? r1 : r0;
        #pragma unroll
        for (int cc = 0; cc < 4; cc++) {
            const int c = c0 + (cc >> 1) * 8 + (cc & 1);
            v[rr][cc] = (r < QN) ? g_me[(size_t)(b * QN + r) * HID + c] : 0.f;
        }
    }

    uint4 ah;
    ah.x = pack_f16(v[0][0], v[0][1]);
    ah.y = pack_f16(v[1][0], v[1][1]);
    ah.z = pack_f16(v[0][2], v[0][3]);
    ah.w = pack_f16(v[1][2], v[1][3]);

    g_AH[((size_t)(b * MROWS + mr) * KSTEPS + ks) * 32 + lane] = ah;
}

// ---------------------------------------------------------------------------
// GEMM (byte-exact R10 — measured 148.6us): out[b,q,p] = sum_c me*mf
// CTA = 64-pixel stripe; 13 warps, one m-tile each, rotated by blockIdx.x.
// B fragments via ldmatrix.x4 from [pixel][kpair] smem (stride 132).
// ---------------------------------------------------------------------------
__global__ __launch_bounds__(GTHREADS) void gemm_kernel(
    const float* __restrict__ mf, float* __restrict__ out)
{
    extern __shared__ uint32_t sB[];               // [64 pixels][BSTRIDE kpairs]

    const int tid  = threadIdx.x;
    const int lane = tid & 31;
    const int w    = tid >> 5;
    const int g    = lane >> 2, i4 = lane & 3;

    const int p0 = blockIdx.x * PTILE;
    const int b  = blockIdx.y;

    const float* mfb  = mf  + (size_t)b * HID * NPIX;
    float*       outb = out + (size_t)b * QN  * NPIX;

    // ---- load + convert B tile: 64 pixels x 256 channels, fp32 -> fp16 ----
    for (int idx = tid; idx < 128 * 16; idx += GTHREADS) {
        const int cp  = idx >> 4;
        const int p4  = idx & 15;
        const float* r0 = mfb + (size_t)(2 * cp)     * NPIX + p0 + p4 * 4;
        const float* r1 = mfb + (size_t)(2 * cp + 1) * NPIX + p0 + p4 * 4;
        float4 v0 = *reinterpret_cast<const float4*>(r0);
        float4 v1 = *reinterpret_cast<const float4*>(r1);
        const float a0[4] = {v0.x, v0.y, v0.z, v0.w};
        const float a1[4] = {v1.x, v1.y, v1.z, v1.w};
        #pragma unroll
        for (int s = 0; s < 4; s++) {
            const int j = (s + p4) & 3;            // stagger -> fewer store conflicts
            sB[(uint32_t)(p4 * 4 + j) * BSTRIDE + cp] = pack_f16(a0[j], a1[j]);
        }
    }
    __syncthreads();

    // ---- compute: warp owns m-tile (w + bx) % 13 ----
    const int mr = (w + (int)blockIdx.x) % NWARP;

    float acc[8][4];
    #pragma unroll
    for (int n = 0; n < 8; n++)
        #pragma unroll
        for (int x = 0; x < 4; x++) acc[n][x] = 0.f;

    const uint4* pAH = g_AH + ((size_t)(b * MROWS + mr) * KSTEPS) * 32 + lane;

    // ldmatrix base: quad q8 selects matrix within x4 (two n-chunks' b0/b1)
    const int q8 = lane >> 3;
    const int r8 = lane & 7;
    const uint32_t sB_addr = (uint32_t)__cvta_generic_to_shared(sB);
    const uint32_t lm_base = sB_addr +
        (uint32_t)((((q8 >> 1) * 8 + r8) * BSTRIDE + (q8 & 1) * 4) * 4);
    const uint32_t J_STRIDE = (uint32_t)(16 * BSTRIDE * 4);   // 2 n-chunks of rows

    #pragma unroll 4
    for (int ks = 0; ks < KSTEPS; ks++) {
        const uint4 ah = pAH[ks * 32];
        const uint32_t ka = lm_base + (uint32_t)(ks * 32);    // ks*8 u32 cols
        #pragma unroll
        for (int j = 0; j < 4; j++) {
            uint32_t b0, b1, b2, b3;
            ldsm_x4(b0, b1, b2, b3, ka + (uint32_t)j * J_STRIDE);
            mma_f16(acc[2 * j],     ah, b0, b1);
            mma_f16(acc[2 * j + 1], ah, b2, b3);
        }
    }

    // ---- epilogue: D frag (16x8) rows = queries, cols = pixel pairs ----
    {
        const int q = mr * 16 + g;
        if (q < QN) {
            float* o = outb + (size_t)q * NPIX + p0 + i4 * 2;
            #pragma unroll
            for (int nc = 0; nc < 8; nc++)
                *reinterpret_cast<float2*>(o + nc * 8) = make_float2(acc[nc][0], acc[nc][1]);
        }
        const int q2 = q + 8;
        if (q2 < QN) {
            float* o2 = outb + (size_t)q2 * NPIX + p0 + i4 * 2;
            #pragma unroll
            for (int nc = 0; nc < 8; nc++)
                *reinterpret_cast<float2*>(o2 + nc * 8) = make_float2(acc[nc][2], acc[nc][3]);
        }
    }
}

// ---------------------------------------------------------------------------
extern "C" void kernel_launch(void* const* d_in, const int* in_sizes, int n_in,
                              void* d_out, int out_size)
{
    const float* queries = (const float*)d_in[0];  // (4, 200, 256)
    const float* mf      = (const float*)d_in[1];  // (4, 256, 256, 256)
    const float* w1      = (const float*)d_in[2];
    const float* b1      = (const float*)d_in[3];
    const float* w2      = (const float*)d_in[4];
    const float* b2      = (const float*)d_in[5];
    float* out = (float*)d_out;                    // (4, 200, 256, 256)

    float* hbuf;  cudaGetSymbolAddress((void**)&hbuf,  g_h);
    float* mebuf; cudaGetSymbolAddress((void**)&mebuf, g_me);

    const int lsm = 2 * HID * LSTRIDE * (int)sizeof(float);     // 73728 B
    cudaFuncSetAttribute(layer_kernel<true >, cudaFuncAttributeMaxDynamicSharedMemorySize, lsm);
    cudaFuncSetAttribute(layer_kernel<false>, cudaFuncAttributeMaxDynamicSharedMemorySize, lsm);

    const int smem = PTILE * BSTRIDE * (int)sizeof(uint32_t);   // 33792 B
    cudaFuncSetAttribute(gemm_kernel, cudaFuncAttributeMaxDynamicSharedMemorySize, smem);

    layer_kernel<true ><<<dim3(NROW / 32, HID / 32), 128, lsm>>>(queries, w1, b1, hbuf);
    layer_kernel<false><<<dim3(NROW / 32, HID / 32), 128, lsm>>>(hbuf,    w2, b2, mebuf);
    pack_kernel<<<NB * MROWS, 512>>>();
    gemm_kernel<<<dim3(NPIX / PTILE, NB), GTHREADS, smem>>>(mf, out);
}